// round 2
// baseline (speedup 1.0000x reference)
#include <cuda_runtime.h>
#include <cuda_bf16.h>

// Problem constants
#define SEQ    512
#define BATCH  64
#define INDIM  128
#define HDIM   512

// Tiling: 16 j-tiles x 8 b-tiles = 128 CTAs, one per SM (all resident -> safe flags)
#define JT     32            // h-columns per CTA
#define BT     8             // batch rows per CTA
#define NJ     (HDIM / JT)   // 16 j-tiles (producers per batch group)
#define NB     (BATCH / BT)  // 8 batch groups
#define NCTA   (NJ * NB)     // 128
#define THREADS 256

// smem: Wh packed (512*32) + Wi packed (128*32) + h tile (8*512) + x tile (8*128)
#define SMEM_FLOATS (HDIM*JT + INDIM*JT + BT*HDIM + BT*INDIM)
#define SMEM_BYTES  (SMEM_FLOATS * 4)

// Per-batch-group cumulative step flags (padded to 128B to avoid false sharing).
// Reset to 0 via cudaMemsetAsync at the start of every kernel_launch (graph-safe).
__device__ unsigned g_flags[NB * 32];

__global__ __launch_bounds__(THREADS, 1)
void rnn_persistent_kernel(const float* __restrict__ x,
                           const float* __restrict__ Wi,
                           const float* __restrict__ bi,
                           const float* __restrict__ Wh,
                           const float* __restrict__ bh,
                           float* __restrict__ out)
{
    extern __shared__ float smem[];
    float* sWh = smem;                    // HDIM*JT  (packed float4-per-(kk,j))
    float* sWi = sWh + HDIM * JT;         // INDIM*JT (same packing)
    float* sh  = sWi + INDIM * JT;        // BT*HDIM  h[t-1] tile
    float* sx  = sh  + BT * HDIM;         // BT*INDIM x[t] tile

    const int tid  = threadIdx.x;
    const int bx   = blockIdx.x;
    const int bt   = bx / NJ;             // batch group
    const int jt   = bx % NJ;             // j tile
    const int j0   = jt * JT;
    const int b0   = bt * BT;
    const int lane = tid & 31;            // j within tile
    const int bb   = tid >> 5;            // b within tile (0..7)
    const int jg   = j0 + lane;

    // ---- One-time weight staging (transposed+packed for conflict-free LDS.128) ----
    // Wh[j0+jj][k] -> sWh[(k>>2)*128 + jj*4 + (k&3)]
    for (int idx = tid; idx < JT * HDIM; idx += THREADS) {
        int jj = idx >> 9;                // / 512
        int k  = idx & (HDIM - 1);
        sWh[(k >> 2) * (JT * 4) + jj * 4 + (k & 3)] = Wh[(j0 + jj) * HDIM + k];
    }
    for (int idx = tid; idx < JT * INDIM; idx += THREADS) {
        int jj = idx >> 7;                // / 128
        int k  = idx & (INDIM - 1);
        sWi[(k >> 2) * (JT * 4) + jj * 4 + (k & 3)] = Wi[(j0 + jj) * INDIM + k];
    }
    const float cb = bi[jg] + bh[jg];
    __syncthreads();

    const float4* sWh4 = (const float4*)sWh;
    const float4* sWi4 = (const float4*)sWi;
    const float4* sh4b = (const float4*)sh + bb * (HDIM / 4);
    const float4* sx4b = (const float4*)sx + bb * (INDIM / 4);
    unsigned* flag = &g_flags[bt * 32];

    for (int t = 0; t < SEQ; t++) {
        // Stage x[t] tile: 8 rows x 128 = 256 float4, one per thread (coalesced)
        {
            const float4* xs = (const float4*)(x + (size_t)t * BATCH * INDIM + b0 * INDIM);
            ((float4*)sx)[tid] = xs[tid];
        }
        // Wait until all 16 producers of this batch group published step t-1
        if (tid == 0 && t > 0) {
            const unsigned target = (unsigned)(NJ * t);
            unsigned v;
            do {
                asm volatile("ld.acquire.gpu.global.u32 %0, [%1];"
                             : "=r"(v) : "l"(flag) : "memory");
            } while (v < target);
        }
        __syncthreads();
        // Stage h[t-1] tile from out: 8 rows x 512 = 1024 float4 (coalesced)
        if (t > 0) {
            const float4* hs = (const float4*)(out + (size_t)(t - 1) * BATCH * HDIM + b0 * HDIM);
            float4* d = (float4*)sh;
            #pragma unroll
            for (int i = 0; i < 4; i++) d[tid + i * THREADS] = hs[tid + i * THREADS];
        }
        __syncthreads();

        // acc = bi+bh + x_t . Wi^T + h_{t-1} . Wh^T   (4 accumulators break FFMA chain)
        float a0 = 0.f, a1 = 0.f, a2 = 0.f, a3 = 0.f;
        {
            const float4* wp = sWi4 + lane;
            #pragma unroll
            for (int kk = 0; kk < INDIM / 4; kk++) {
                float4 xv = sx4b[kk];         // broadcast within warp
                float4 wv = wp[kk * JT];      // conflict-free, lane-consecutive
                a0 += xv.x * wv.x; a1 += xv.y * wv.y;
                a2 += xv.z * wv.z; a3 += xv.w * wv.w;
            }
        }
        if (t > 0) {
            const float4* wp = sWh4 + lane;
            #pragma unroll 8
            for (int kk = 0; kk < HDIM / 4; kk++) {
                float4 hv = sh4b[kk];
                float4 wv = wp[kk * JT];
                a0 += hv.x * wv.x; a1 += hv.y * wv.y;
                a2 += hv.z * wv.z; a3 += hv.w * wv.w;
            }
        }
        const float val = tanhf(cb + (a0 + a1) + (a2 + a3));
        out[(size_t)t * BATCH * HDIM + (b0 + bb) * HDIM + jg] = val;
        if (t == SEQ - 1)   // h_last appended after h_seq
            out[(size_t)SEQ * BATCH * HDIM + (b0 + bb) * HDIM + jg] = val;

        __threadfence();     // make this CTA's h[t] visible gpu-wide
        __syncthreads();     // all stores+fences done before publish; also guards smem reuse
        if (tid == 0) atomicAdd(flag, 1u);
    }
}

extern "C" void kernel_launch(void* const* d_in, const int* in_sizes, int n_in,
                              void* d_out, int out_size)
{
    const float* x  = (const float*)d_in[0];
    const float* Wi = (const float*)d_in[1];
    const float* bi = (const float*)d_in[2];
    const float* Wh = (const float*)d_in[3];
    const float* bh = (const float*)d_in[4];
    float* out = (float*)d_out;

    (void)in_sizes; (void)n_in; (void)out_size;

    void* flagsPtr = nullptr;
    cudaGetSymbolAddress(&flagsPtr, g_flags);
    cudaMemsetAsync(flagsPtr, 0, sizeof(g_flags), 0);

    cudaFuncSetAttribute(rnn_persistent_kernel,
                         cudaFuncAttributeMaxDynamicSharedMemorySize, SMEM_BYTES);
    rnn_persistent_kernel<<<NCTA, THREADS, SMEM_BYTES>>>(x, Wi, bi, Wh, bh, out);
}

// round 3
// speedup vs baseline: 1.6719x; 1.6719x over previous
#include <cuda_runtime.h>
#include <cuda_bf16.h>

// Problem constants
#define SEQ    512
#define BATCH  64
#define INDIM  128
#define HDIM   512

// Tiling: 16 j-tiles x 8 b-tiles = 128 CTAs, one per SM (all resident -> safe flags)
#define JT     32            // h-columns per CTA
#define BT     8             // batch rows per CTA
#define NJ     (HDIM / JT)   // 16 j-tiles (producers per batch group)
#define NB     (BATCH / BT)  // 8 batch groups
#define NCTA   (NJ * NB)     // 128
#define THREADS 256
#define NWARP   8

// K-chunks (float4 granularity) per warp
#define WH_CHUNKS_TOT (HDIM / 4)            // 128
#define WI_CHUNKS_TOT (INDIM / 4)           // 32
#define WH_CPW (WH_CHUNKS_TOT / NWARP)      // 16
#define WI_CPW (WI_CHUNKS_TOT / NWARP)      // 4

// Reduction scratch: R[lane][b*8 + w], row stride 73 (odd -> conflict-free)
#define RED_STRIDE 73
#define RED_FLOATS (32 * RED_STRIDE)

// smem: Wh packed + Wi packed + h tile + x tile + reduction scratch
#define SMEM_FLOATS (HDIM*JT + INDIM*JT + BT*HDIM + BT*INDIM + RED_FLOATS)
#define SMEM_BYTES  (SMEM_FLOATS * 4)

// Per-batch-group cumulative step flags (padded to 128B).
// Reset via cudaMemsetAsync every kernel_launch (graph-safe, replay-safe).
__device__ unsigned g_flags[NB * 32];

// Packed dual-FMA: acc.{lo,hi} += a.{lo,hi} * b.{lo,hi}
#define FMA2(acc, a, b) \
    asm("fma.rn.f32x2 %0, %1, %2, %0;" : "+l"(acc) : "l"(a), "l"(b))

__global__ __launch_bounds__(THREADS, 1)
void rnn_persistent_kernel(const float* __restrict__ x,
                           const float* __restrict__ Wi,
                           const float* __restrict__ bi,
                           const float* __restrict__ Wh,
                           const float* __restrict__ bh,
                           float* __restrict__ out)
{
    extern __shared__ float smem[];
    float* sWh  = smem;                    // HDIM*JT  packed: [kc][j][4]
    float* sWi  = sWh + HDIM * JT;         // INDIM*JT same packing
    float* sh   = sWi + INDIM * JT;        // BT*HDIM  h[t-1] tile, row-major [b][k]
    float* sx   = sh  + BT * HDIM;         // BT*INDIM x[t] tile,   row-major [b][k]
    float* sred = sx  + BT * INDIM;        // 32*73 reduction scratch

    const int tid  = threadIdx.x;
    const int bx   = blockIdx.x;
    const int bt   = bx / NJ;              // batch group
    const int jt   = bx % NJ;              // j tile
    const int j0   = jt * JT;
    const int b0   = bt * BT;
    const int lane = tid & 31;             // j within tile (both roles)
    const int w    = tid >> 5;             // warp id = K-slice owner
    const int jg   = j0 + lane;

    // ---- One-time weight staging (transposed+packed for conflict-free LDS.128) ----
    // Wh[j0+jj][k] -> sWh[(k>>2)*128 + jj*4 + (k&3)]
    for (int idx = tid; idx < JT * HDIM; idx += THREADS) {
        int jj = idx >> 9;
        int k  = idx & (HDIM - 1);
        sWh[(k >> 2) * (JT * 4) + jj * 4 + (k & 3)] = Wh[(j0 + jj) * HDIM + k];
    }
    for (int idx = tid; idx < JT * INDIM; idx += THREADS) {
        int jj = idx >> 7;
        int k  = idx & (INDIM - 1);
        sWi[(k >> 2) * (JT * 4) + jj * 4 + (k & 3)] = Wi[(j0 + jj) * INDIM + k];
    }
    const float cb = bi[jg] + bh[jg];
    __syncthreads();

    const ulonglong2* sWh2 = (const ulonglong2*)sWh;   // one elem = float4 = 2 f32x2
    const ulonglong2* sWi2 = (const ulonglong2*)sWi;
    const ulonglong2* sh2  = (const ulonglong2*)sh;    // [b*128 + kc]
    const ulonglong2* sx2  = (const ulonglong2*)sx;    // [b*32  + kc]
    unsigned* flag = &g_flags[bt * 32];

    for (int t = 0; t < SEQ; t++) {
        // Stage x[t] tile: 8 rows x 128 = 256 float4, one per thread (coalesced)
        {
            const float4* xs = (const float4*)(x + (size_t)t * BATCH * INDIM + b0 * INDIM);
            ((float4*)sx)[tid] = xs[tid];
        }
        // Wait until all 16 producers of this batch group published step t-1
        if (tid == 0 && t > 0) {
            const unsigned target = (unsigned)(NJ * t);
            unsigned v;
            do {
                asm volatile("ld.acquire.gpu.global.u32 %0, [%1];"
                             : "=r"(v) : "l"(flag) : "memory");
            } while (v < target);
        }
        __syncthreads();
        // Stage h[t-1] tile from out: 8 rows x 512 = 1024 float4 (coalesced)
        if (t > 0) {
            const float4* hs = (const float4*)(out + (size_t)(t - 1) * BATCH * HDIM + b0 * HDIM);
            float4* d = (float4*)sh;
            #pragma unroll
            for (int i = 0; i < 4; i++) d[tid + i * THREADS] = hs[tid + i * THREADS];
        }
        __syncthreads();

        // Partial dot products: this warp covers its K-slice, ALL 8 batches.
        // acc2[b] = {sum over even-pair k, sum over odd-pair k} (f32x2 packed over K)
        unsigned long long acc2[BT];
        #pragma unroll
        for (int b = 0; b < BT; b++) acc2[b] = 0ull;   // {0.f, 0.f}

        {   // Wi part: chunks [w*4, w*4+4)
            const int c0 = w * WI_CPW;
            #pragma unroll
            for (int c = 0; c < WI_CPW; c++) {
                const int kc = c0 + c;
                ulonglong2 wv = sWi2[kc * JT + lane];       // conflict-free
                #pragma unroll
                for (int b = 0; b < BT; b++) {
                    ulonglong2 hv = sx2[b * (INDIM / 4) + kc];   // broadcast
                    FMA2(acc2[b], wv.x, hv.x);
                    FMA2(acc2[b], wv.y, hv.y);
                }
            }
        }
        if (t > 0) {  // Wh part: chunks [w*16, w*16+16)
            const int c0 = w * WH_CPW;
            #pragma unroll 4
            for (int c = 0; c < WH_CPW; c++) {
                const int kc = c0 + c;
                ulonglong2 wv = sWh2[kc * JT + lane];
                #pragma unroll
                for (int b = 0; b < BT; b++) {
                    ulonglong2 hv = sh2[b * (HDIM / 4) + kc];    // broadcast
                    FMA2(acc2[b], wv.x, hv.x);
                    FMA2(acc2[b], wv.y, hv.y);
                }
            }
        }

        // Spill partials: R[lane][b*8 + w]  (row stride 73 -> conflict-free)
        #pragma unroll
        for (int b = 0; b < BT; b++) {
            union { unsigned long long u; float2 f; } cvt; cvt.u = acc2[b];
            sred[lane * RED_STRIDE + b * NWARP + w] = cvt.f.x + cvt.f.y;
        }
        __syncthreads();

        // Reduce across 8 warps: thread (bb = w role reused, lane = j)
        {
            const int bb = w;  // reader role: warp index == batch index
            const float* r = &sred[lane * RED_STRIDE + bb * NWARP];
            float s = ((r[0] + r[1]) + (r[2] + r[3])) + ((r[4] + r[5]) + (r[6] + r[7]));
            const float val = tanhf(cb + s);
            out[(size_t)t * BATCH * HDIM + (b0 + bb) * HDIM + jg] = val;
            if (t == SEQ - 1)   // h_last appended after h_seq
                out[(size_t)SEQ * BATCH * HDIM + (b0 + bb) * HDIM + jg] = val;
        }

        __threadfence();     // make this CTA's h[t] visible gpu-wide
        __syncthreads();     // all stores+fences done before publish; guards smem reuse
        if (tid == 0) atomicAdd(flag, 1u);
    }
}

extern "C" void kernel_launch(void* const* d_in, const int* in_sizes, int n_in,
                              void* d_out, int out_size)
{
    const float* x  = (const float*)d_in[0];
    const float* Wi = (const float*)d_in[1];
    const float* bi = (const float*)d_in[2];
    const float* Wh = (const float*)d_in[3];
    const float* bh = (const float*)d_in[4];
    float* out = (float*)d_out;

    (void)in_sizes; (void)n_in; (void)out_size;

    void* flagsPtr = nullptr;
    cudaGetSymbolAddress(&flagsPtr, g_flags);
    cudaMemsetAsync(flagsPtr, 0, sizeof(g_flags), 0);

    cudaFuncSetAttribute(rnn_persistent_kernel,
                         cudaFuncAttributeMaxDynamicSharedMemorySize, SMEM_BYTES);
    rnn_persistent_kernel<<<NCTA, THREADS, SMEM_BYTES>>>(x, Wi, bi, Wh, bh, out);
}